// round 2
// baseline (speedup 1.0000x reference)
#include <cuda_runtime.h>
#include <cuda_bf16.h>

#define N_POINTS 2097152
#define NHEADS   16
#define FEAT     2
#define D_IN     32
#define HID      64
#define NOUT     3
#define M_TBL    524288

#define THREADS  128
#define BLOCKS   (N_POINTS / THREADS)   // 16384, exactly 1 point per thread

// Weights live in constant memory: warp-uniform accesses become LDCU -> UR,
// feeding FFMA via the uniform operand path. Zero shared-memory crossbar
// traffic (which was the Round-1 bottleneck at ~84% L1 throughput).
__constant__ float cW1[D_IN * HID];   // 8 KB
__constant__ float cb1[HID];
__constant__ float cW2[HID * HID];    // 16 KB
__constant__ float cb2[HID];
__constant__ float cW3[HID * HID];    // 16 KB
__constant__ float cb3[HID];
__constant__ float cW4[HID * NOUT];
__constant__ float cb4[NOUT];

__global__ __launch_bounds__(THREADS)
void ngp_mlp_kernel(const int* __restrict__ idx,
                    const float* __restrict__ tables,   // [H, M, F]
                    float* __restrict__ out)
{
    const int n = blockIdx.x * THREADS + threadIdx.x;   // < N_POINTS always

    // ---- gather: x[32] = concat_h tables[h][idx[n,h]] ----
    float x[D_IN];
    #pragma unroll
    for (int h = 0; h < NHEADS; h += 4) {
        int4 iv = *reinterpret_cast<const int4*>(idx + (long)n * NHEADS + h);
        float2 v0 = *reinterpret_cast<const float2*>(
            tables + ((long)(h + 0) * M_TBL + iv.x) * FEAT);
        float2 v1 = *reinterpret_cast<const float2*>(
            tables + ((long)(h + 1) * M_TBL + iv.y) * FEAT);
        float2 v2 = *reinterpret_cast<const float2*>(
            tables + ((long)(h + 2) * M_TBL + iv.z) * FEAT);
        float2 v3 = *reinterpret_cast<const float2*>(
            tables + ((long)(h + 3) * M_TBL + iv.w) * FEAT);
        x[(h + 0) * FEAT + 0] = v0.x; x[(h + 0) * FEAT + 1] = v0.y;
        x[(h + 1) * FEAT + 0] = v1.x; x[(h + 1) * FEAT + 1] = v1.y;
        x[(h + 2) * FEAT + 0] = v2.x; x[(h + 2) * FEAT + 1] = v2.y;
        x[(h + 3) * FEAT + 0] = v3.x; x[(h + 3) * FEAT + 1] = v3.y;
    }

    // ---- layer 1: 32 -> 64, relu ----
    float h1[HID];
    #pragma unroll
    for (int j = 0; j < HID; j++) h1[j] = cb1[j];
    #pragma unroll 4
    for (int i = 0; i < D_IN; i++) {
        const float xi = x[i];
        #pragma unroll
        for (int j = 0; j < HID; j++)
            h1[j] = fmaf(xi, cW1[i * HID + j], h1[j]);
    }
    #pragma unroll
    for (int j = 0; j < HID; j++) h1[j] = fmaxf(h1[j], 0.0f);

    // ---- layer 2: 64 -> 64, relu ----
    float h2[HID];
    #pragma unroll
    for (int j = 0; j < HID; j++) h2[j] = cb2[j];
    #pragma unroll 4
    for (int i = 0; i < HID; i++) {
        const float xi = h1[i];
        #pragma unroll
        for (int j = 0; j < HID; j++)
            h2[j] = fmaf(xi, cW2[i * HID + j], h2[j]);
    }
    #pragma unroll
    for (int j = 0; j < HID; j++) h2[j] = fmaxf(h2[j], 0.0f);

    // ---- layer 3: 64 -> 64, relu (reuse h1) ----
    #pragma unroll
    for (int j = 0; j < HID; j++) h1[j] = cb3[j];
    #pragma unroll 4
    for (int i = 0; i < HID; i++) {
        const float xi = h2[i];
        #pragma unroll
        for (int j = 0; j < HID; j++)
            h1[j] = fmaf(xi, cW3[i * HID + j], h1[j]);
    }
    #pragma unroll
    for (int j = 0; j < HID; j++) h1[j] = fmaxf(h1[j], 0.0f);

    // ---- layer 4: 64 -> 3 ----
    float o0 = cb4[0], o1 = cb4[1], o2 = cb4[2];
    #pragma unroll
    for (int i = 0; i < HID; i++) {
        const float xi = h1[i];
        o0 = fmaf(xi, cW4[i * NOUT + 0], o0);
        o1 = fmaf(xi, cW4[i * NOUT + 1], o1);
        o2 = fmaf(xi, cW4[i * NOUT + 2], o2);
    }
    out[(long)n * NOUT + 0] = o0;
    out[(long)n * NOUT + 1] = o1;
    out[(long)n * NOUT + 2] = o2;
}

extern "C" void kernel_launch(void* const* d_in, const int* in_sizes, int n_in,
                              void* d_out, int out_size)
{
    const int*   idx    = (const int*)  d_in[0];
    const float* tables = (const float*)d_in[1];

    // Stage weights into constant memory (D2D async memcpys: graph-capturable)
    cudaMemcpyToSymbolAsync(cW1, d_in[2], D_IN * HID * sizeof(float), 0,
                            cudaMemcpyDeviceToDevice, 0);
    cudaMemcpyToSymbolAsync(cb1, d_in[3], HID * sizeof(float), 0,
                            cudaMemcpyDeviceToDevice, 0);
    cudaMemcpyToSymbolAsync(cW2, d_in[4], HID * HID * sizeof(float), 0,
                            cudaMemcpyDeviceToDevice, 0);
    cudaMemcpyToSymbolAsync(cb2, d_in[5], HID * sizeof(float), 0,
                            cudaMemcpyDeviceToDevice, 0);
    cudaMemcpyToSymbolAsync(cW3, d_in[6], HID * HID * sizeof(float), 0,
                            cudaMemcpyDeviceToDevice, 0);
    cudaMemcpyToSymbolAsync(cb3, d_in[7], HID * sizeof(float), 0,
                            cudaMemcpyDeviceToDevice, 0);
    cudaMemcpyToSymbolAsync(cW4, d_in[8], HID * NOUT * sizeof(float), 0,
                            cudaMemcpyDeviceToDevice, 0);
    cudaMemcpyToSymbolAsync(cb4, d_in[9], NOUT * sizeof(float), 0,
                            cudaMemcpyDeviceToDevice, 0);

    float* out = (float*)d_out;
    ngp_mlp_kernel<<<BLOCKS, THREADS>>>(idx, tables, out);
}

// round 3
// speedup vs baseline: 2.3217x; 2.3217x over previous
#include <cuda_runtime.h>

#define NHEADS   16
#define M_TBL    524288
#define D_IN     32
#define HID      64
#define NOUT     3
#define TILE     128
#define THREADS  256
#define NBLOCKS  16384      // 16384 * 128 = 2,097,152 points exactly
#define STRIDE   132        // padded point stride (bank-conflict-free row starts)

// dynamic smem layout (float offsets)
#define OFF_A0   0
#define SZ_A0    (D_IN * STRIDE)        // 4224
#define OFF_B1   (OFF_A0 + SZ_A0)       // 4224
#define SZ_B     (HID * STRIDE)         // 8448
#define OFF_B2   (OFF_B1 + SZ_B)        // 12672
#define OFF_WB   (OFF_B2 + SZ_B)        // 21120
#define SZ_WB    (HID * HID)            // 4096
#define OFF_SM   (OFF_WB + SZ_WB)       // 25216  (b1|b2|b3|W4|b4)
#define SZ_SM    512
#define SMEM_FLOATS (OFF_SM + SZ_SM)    // 25728
#define SMEM_BYTES  (SMEM_FLOATS * 4)   // 102912 bytes -> 2 CTAs/SM

// packed f32x2 FMA: d = a*b + d  (per-half)
#define FMA2(acc, a, w) \
    asm("fma.rn.f32x2 %0, %1, %2, %0;" : "+l"(acc) : "l"(a), "l"(w))
#define PACK2(d, s) \
    asm("mov.b64 %0, {%1, %1};" : "=l"(d) : "f"(s))
#define UNPACK2(lo, hi, s) \
    asm("mov.b64 {%0, %1}, %2;" : "=f"(lo), "=f"(hi) : "l"(s))

// One 64-wide layer over a 128-point tile.
// A:   [K][STRIDE] activations (point-major rows)
// W:   [K][64] weights in smem
// out: [64][STRIDE], relu applied
template<int K>
__device__ __forceinline__ void layer_compute(const float* __restrict__ A,
                                              float* __restrict__ Bout,
                                              const float* __restrict__ W,
                                              const float* __restrict__ bias,
                                              int tid)
{
    const int j0 = (tid & 15) * 4;       // 16 j-tiles of 4
    const int p0 = (tid >> 4) * 8;       // 16 p-tiles of 8 (4 f32x2 pairs)

    unsigned long long acc[16];
    #pragma unroll
    for (int jj = 0; jj < 4; jj++) {
        unsigned long long bd;
        PACK2(bd, bias[j0 + jj]);
        #pragma unroll
        for (int pp = 0; pp < 4; pp++) acc[jj * 4 + pp] = bd;
    }

    #pragma unroll 4
    for (int k = 0; k < K; k++) {
        const ulonglong2 a01 =
            *reinterpret_cast<const ulonglong2*>(&A[k * STRIDE + p0]);
        const ulonglong2 a23 =
            *reinterpret_cast<const ulonglong2*>(&A[k * STRIDE + p0 + 4]);
        const float4 w = *reinterpret_cast<const float4*>(&W[k * HID + j0]);
        unsigned long long wd0, wd1, wd2, wd3;
        PACK2(wd0, w.x); PACK2(wd1, w.y); PACK2(wd2, w.z); PACK2(wd3, w.w);

        FMA2(acc[ 0], a01.x, wd0); FMA2(acc[ 1], a01.y, wd0);
        FMA2(acc[ 2], a23.x, wd0); FMA2(acc[ 3], a23.y, wd0);
        FMA2(acc[ 4], a01.x, wd1); FMA2(acc[ 5], a01.y, wd1);
        FMA2(acc[ 6], a23.x, wd1); FMA2(acc[ 7], a23.y, wd1);
        FMA2(acc[ 8], a01.x, wd2); FMA2(acc[ 9], a01.y, wd2);
        FMA2(acc[10], a23.x, wd2); FMA2(acc[11], a23.y, wd2);
        FMA2(acc[12], a01.x, wd3); FMA2(acc[13], a01.y, wd3);
        FMA2(acc[14], a23.x, wd3); FMA2(acc[15], a23.y, wd3);
    }

    // relu + store transposed rows
    #pragma unroll
    for (int jj = 0; jj < 4; jj++) {
        float v[8];
        #pragma unroll
        for (int pp = 0; pp < 4; pp++)
            UNPACK2(v[2 * pp], v[2 * pp + 1], acc[jj * 4 + pp]);
        #pragma unroll
        for (int q = 0; q < 8; q++) v[q] = fmaxf(v[q], 0.0f);
        float* dst = &Bout[(j0 + jj) * STRIDE + p0];
        *reinterpret_cast<float4*>(dst)     = make_float4(v[0], v[1], v[2], v[3]);
        *reinterpret_cast<float4*>(dst + 4) = make_float4(v[4], v[5], v[6], v[7]);
    }
}

__global__ __launch_bounds__(THREADS)
void ngp_tiled_kernel(const int* __restrict__ idx,
                      const float* __restrict__ tables,
                      const float* __restrict__ gW1, const float* __restrict__ gb1,
                      const float* __restrict__ gW2, const float* __restrict__ gb2,
                      const float* __restrict__ gW3, const float* __restrict__ gb3,
                      const float* __restrict__ gW4, const float* __restrict__ gb4,
                      float* __restrict__ out)
{
    extern __shared__ float smem[];
    float* A0  = smem + OFF_A0;
    float* B1  = smem + OFF_B1;
    float* B2  = smem + OFF_B2;
    float* WB  = smem + OFF_WB;
    float* SMC = smem + OFF_SM;   // [0:64) b1, [64:128) b2, [128:192) b3,
                                  // [192:384) W4, [384:387) b4
    const int tid = threadIdx.x;
    const long pbase = (long)blockIdx.x * TILE;

    // ---- stage W1 (2048 floats) into WB ----
    {
        const float4* src = reinterpret_cast<const float4*>(gW1);
        float4* dst = reinterpret_cast<float4*>(WB);
        dst[tid]       = src[tid];
        dst[tid + 256] = src[tid + 256];
    }
    // ---- stage small constants ----
    if (tid < HID) {
        SMC[tid]       = gb1[tid];
        SMC[64 + tid]  = gb2[tid];
        SMC[128 + tid] = gb3[tid];
    }
    if (tid < HID * NOUT) SMC[192 + tid] = gW4[tid];
    if (tid < NOUT)       SMC[384 + tid] = gb4[tid];

    // ---- gather: A0[k][p] (2 threads per point, 8 heads each) ----
    {
        const int p  = tid >> 1;
        const int hs = (tid & 1) * 8;
        const int* ip = idx + (pbase + p) * NHEADS + hs;
        const int4 i0 = *reinterpret_cast<const int4*>(ip);
        const int4 i1 = *reinterpret_cast<const int4*>(ip + 4);
        const int ii[8] = {i0.x, i0.y, i0.z, i0.w, i1.x, i1.y, i1.z, i1.w};
        #pragma unroll
        for (int hh = 0; hh < 8; hh++) {
            const int h = hs + hh;
            const float2 v = *reinterpret_cast<const float2*>(
                tables + ((long)h * M_TBL + ii[hh]) * 2);
            A0[(2 * h)     * STRIDE + p] = v.x;
            A0[(2 * h + 1) * STRIDE + p] = v.y;
        }
    }
    __syncthreads();

    // prefetch W2 into registers while layer 1 computes
    float4 pf[4];
    #pragma unroll
    for (int q = 0; q < 4; q++)
        pf[q] = reinterpret_cast<const float4*>(gW2)[tid + q * 256];

    layer_compute<D_IN>(A0, B1, WB, SMC, tid);          // layer 1: 32 -> 64
    __syncthreads();
    #pragma unroll
    for (int q = 0; q < 4; q++)
        reinterpret_cast<float4*>(WB)[tid + q * 256] = pf[q];
    __syncthreads();

    // prefetch W3 while layer 2 computes
    #pragma unroll
    for (int q = 0; q < 4; q++)
        pf[q] = reinterpret_cast<const float4*>(gW3)[tid + q * 256];

    layer_compute<HID>(B1, B2, WB, SMC + 64, tid);      // layer 2: 64 -> 64
    __syncthreads();
    #pragma unroll
    for (int q = 0; q < 4; q++)
        reinterpret_cast<float4*>(WB)[tid + q * 256] = pf[q];
    __syncthreads();

    layer_compute<HID>(B2, B1, WB, SMC + 128, tid);     // layer 3: 64 -> 64
    __syncthreads();

    // ---- layer 4: 64 -> 3, one thread per point ----
    if (tid < TILE) {
        const int p = tid;
        float o0 = SMC[384], o1 = SMC[385], o2 = SMC[386];
        #pragma unroll 8
        for (int k = 0; k < HID; k++) {
            const float a = B1[k * STRIDE + p];
            o0 = fmaf(a, SMC[192 + k * NOUT + 0], o0);
            o1 = fmaf(a, SMC[192 + k * NOUT + 1], o1);
            o2 = fmaf(a, SMC[192 + k * NOUT + 2], o2);
        }
        float* op = out + (pbase + p) * NOUT;
        op[0] = o0; op[1] = o1; op[2] = o2;
    }
}

extern "C" void kernel_launch(void* const* d_in, const int* in_sizes, int n_in,
                              void* d_out, int out_size)
{
    const int*   idx    = (const int*)  d_in[0];
    const float* tables = (const float*)d_in[1];

    // opt-in to >48KB dynamic smem (idempotent; executes immediately, not a
    // stream op, so it is graph-capture safe)
    static int smem_set = 0;
    if (!smem_set) {
        cudaFuncSetAttribute(ngp_tiled_kernel,
                             cudaFuncAttributeMaxDynamicSharedMemorySize,
                             SMEM_BYTES);
        smem_set = 1;
    }

    ngp_tiled_kernel<<<NBLOCKS, THREADS, SMEM_BYTES>>>(
        idx, tables,
        (const float*)d_in[2], (const float*)d_in[3],
        (const float*)d_in[4], (const float*)d_in[5],
        (const float*)d_in[6], (const float*)d_in[7],
        (const float*)d_in[8], (const float*)d_in[9],
        (float*)d_out);
}